// round 3
// baseline (speedup 1.0000x reference)
#include <cuda_runtime.h>
#include <cstdint>
#include <math.h>

#define BB   128      // batch
#define TT   256      // timesteps
#define HH   512      // hidden
#define EE   300      // embed dim
#define GG   2048     // 4H
#define BH   (BB*HH)

// ---------------- device scratch (static, no allocation) ----------------
__device__ float g_xproj[(size_t)TT * GG * BB];   // [t][col][b]  256MB
__device__ float g_Wp0[(size_t)GG * HH];          // packed [cta][16][512]
__device__ float g_Wp1[(size_t)GG * 2 * HH];      // packed [cta][16][1024]
__device__ float g_h0[2 * BH];                    // ping-pong
__device__ float g_h1[2 * BH];
__device__ float g_c0[BH];
__device__ float g_c1[BH];
__device__ unsigned g_bar_count;
__device__ unsigned g_bar_gen;
__device__ int g_odd_nonzero;                     // 1 -> x buffer is int32 layout

// ---------------- helpers ----------------
__device__ __forceinline__ unsigned long long bcast2(float v) {
    unsigned long long r;
    asm("mov.b64 %0, {%1, %1};" : "=l"(r) : "f"(v));
    return r;
}
__device__ __forceinline__ unsigned long long fma2(unsigned long long a,
                                                   unsigned long long b,
                                                   unsigned long long c) {
    unsigned long long d;
    asm("fma.rn.f32x2 %0, %1, %2, %3;" : "=l"(d) : "l"(a), "l"(b), "l"(c));
    return d;
}
__device__ __forceinline__ float2 unpk2(unsigned long long v) {
    float2 f;
    asm("mov.b64 {%0, %1}, %2;" : "=f"(f.x), "=f"(f.y) : "l"(v));
    return f;
}
__device__ __forceinline__ float sigf(float x) { return 1.0f / (1.0f + expf(-x)); }

__device__ __forceinline__ void grid_barrier() {
    __syncthreads();
    if (threadIdx.x == 0) {
        __threadfence();
        unsigned gen = *((volatile unsigned*)&g_bar_gen);
        unsigned ticket = atomicAdd(&g_bar_count, 1u);
        if (ticket == gridDim.x - 1) {
            atomicExch(&g_bar_count, 0u);
            __threadfence();
            atomicAdd(&g_bar_gen, 1u);
        } else {
            while (*((volatile unsigned*)&g_bar_gen) == gen) {}
            __threadfence();
        }
    }
    __syncthreads();
}

// ---------------- kernel D: detect int32 vs int64 layout of x ----------------
// Safe under both layouts: scans only words [0, nwords) where nwords = element
// count (int64 buffer has 2*nwords words). int64 layout => odd words (high
// halves) are all zero. int32 layout => odd words are random indices.
__global__ void detect_kernel(const int* __restrict__ xw, int nwords) {
    int i = blockIdx.x * blockDim.x + threadIdx.x;
    int odd = 2 * i + 1;
    if (odd < nwords && xw[odd] != 0) atomicOr(&g_odd_nonzero, 1);
}

// ---------------- kernel P: pack weights + zero state ----------------
// Wp0[c][l][k] = W0[E + k][512*(l/4) + c*4 + (l%4)]   (k in 0..511)
// Wp1[c][l][k] = W1[k]    [512*(l/4) + c*4 + (l%4)]   (k in 0..1023)
__global__ void pack_kernel(const float* __restrict__ W0,
                            const float* __restrict__ W1) {
    size_t i = (size_t)blockIdx.x * blockDim.x + threadIdx.x;
    const size_t N0 = (size_t)GG * HH;        // 1,048,576
    const size_t N1 = (size_t)GG * 2 * HH;    // 2,097,152
    if (i < N0) {
        int c = (int)(i / (16 * HH));
        int r = (int)(i % (16 * HH));
        int l = r / HH, k = r % HH;
        int gcol = ((l >> 2) << 9) + (c << 2) + (l & 3);
        g_Wp0[i] = W0[(size_t)(EE + k) * GG + gcol];
    }
    if (i < N1) {
        int c = (int)(i / (16 * 2 * HH));
        int r = (int)(i % (16 * 2 * HH));
        int l = r / (2 * HH), k = r % (2 * HH);
        int gcol = ((l >> 2) << 9) + (c << 2) + (l & 3);
        g_Wp1[i] = W1[(size_t)k * GG + gcol];
    }
    if (i < BH) {
        g_h0[i] = 0.0f; g_h1[i] = 0.0f;
        g_c0[i] = 0.0f; g_c1[i] = 0.0f;
    }
    if (i == 0) { g_bar_count = 0; g_odd_nonzero = 0; }
}

// ---------------- kernel A: xproj[t][col][b] = b0[col] + emb[x[b,t]] . W0x ----------------
// grid: (16 col-tiles of 128, 256 timesteps), 256 threads.
// thread: 8 cols x 8 batch.
__global__ void __launch_bounds__(256) xproj_kernel(const int* __restrict__ xw,
                                                    const float* __restrict__ emb,
                                                    const float* __restrict__ W0,
                                                    const float* __restrict__ bias0,
                                                    int vmax) {
    __shared__ float s_emb[88 * 128];   // [e][b], 45KB
    __shared__ int s_row[BB];
    const int t = blockIdx.y;
    const int colbase = blockIdx.x * 128;
    const int tid = threadIdx.x;

    const int stride = g_odd_nonzero ? 1 : 2;  // 1 = int32 layout, 2 = int64 layout
    if (tid < BB) {
        int idx = xw[((size_t)tid * TT + t) * stride];
        idx = idx < 0 ? 0 : (idx > vmax ? vmax : idx);
        s_row[tid] = idx;
    }

    const int cp8 = tid & 15;        // col group: 8 cols
    const int bg  = tid >> 4;        // batch group: 8 b
    const int cb  = colbase + cp8 * 8;
    const int bi  = bg * 8;

    unsigned long long acc[8][4];
#pragma unroll
    for (int c8 = 0; c8 < 8; c8++) {
        unsigned long long bv = bcast2(bias0[cb + c8]);
#pragma unroll
        for (int p = 0; p < 4; p++) acc[c8][p] = bv;
    }
    __syncthreads();

    for (int e0 = 0; e0 < EE; e0 += 88) {
        const int ec = (EE - e0 < 88) ? (EE - e0) : 88;   // 88,88,88,36 (all %4==0)
        const int f4cnt = ec >> 2;
        // cooperative gathered load: s_emb[e][b]
        for (int fi = tid; fi < 128 * f4cnt; fi += 256) {
            int b = fi / f4cnt, j = fi % f4cnt;
            const float4 v = *(const float4*)&emb[(size_t)s_row[b] * EE + e0 + j * 4];
            s_emb[(j * 4 + 0) * 128 + b] = v.x;
            s_emb[(j * 4 + 1) * 128 + b] = v.y;
            s_emb[(j * 4 + 2) * 128 + b] = v.z;
            s_emb[(j * 4 + 3) * 128 + b] = v.w;
        }
        __syncthreads();

#pragma unroll 4
        for (int e = 0; e < ec; e++) {
            const float* wrow = W0 + (size_t)(e0 + e) * GG + cb;
            const float4 w0v = *(const float4*)wrow;
            const float4 w1v = *(const float4*)(wrow + 4);
            float wv[8] = {w0v.x, w0v.y, w0v.z, w0v.w, w1v.x, w1v.y, w1v.z, w1v.w};
            const ulonglong2 hA = *(const ulonglong2*)&s_emb[e * 128 + bi];
            const ulonglong2 hB = *(const ulonglong2*)&s_emb[e * 128 + bi + 4];
            unsigned long long hp[4] = {hA.x, hA.y, hB.x, hB.y};
#pragma unroll
            for (int c8 = 0; c8 < 8; c8++) {
                unsigned long long w2 = bcast2(wv[c8]);
#pragma unroll
                for (int p = 0; p < 4; p++) acc[c8][p] = fma2(hp[p], w2, acc[c8][p]);
            }
        }
        __syncthreads();
    }

#pragma unroll
    for (int c8 = 0; c8 < 8; c8++) {
        size_t base = ((size_t)t * GG + cb + c8) * BB + bi;
#pragma unroll
        for (int p = 0; p < 4; p++)
            *(unsigned long long*)&g_xproj[base + p * 2] = acc[c8][p];
    }
}

// ---------------- kernel B: persistent recurrent loop ----------------
// 128 CTAs x 256 threads. CTA c owns h-cols [c*4, c*4+4) across all 4 gates.
// thread: col-pair cp (2 of the CTA's 16 g-cols) x 4 batch rows.
// All cross-CTA h traffic goes through L2 (__ldcg/__stcg): L1 is not coherent
// across SMs and these lines would otherwise be stale from 2 steps earlier.
__global__ void __launch_bounds__(256, 1) lstm_kernel(const float* __restrict__ bias1,
                                                      const float* __restrict__ Wd,
                                                      const float* __restrict__ bd,
                                                      float* __restrict__ out) {
    __shared__ float s_h[64 * 128];    // [k][b] chunk, 32KB
    __shared__ float s_g[16 * 132];    // gate staging, padded

    const int c   = blockIdx.x;
    const int tid = threadIdx.x;
    const int cp  = tid & 7;
    const int bg  = tid >> 3;
    const int bb  = bg * 4;
    const int l0  = cp * 2;
    const int l1  = cp * 2 + 1;
    const int gc0 = ((l0 >> 2) << 9) + (c << 2) + (l0 & 3);
    const int gc1 = ((l1 >> 2) << 9) + (c << 2) + (l1 & 3);

    const float* wp0a = g_Wp0 + ((size_t)c * 16 + l0) * HH;
    const float* wp0b = g_Wp0 + ((size_t)c * 16 + l1) * HH;
    const float* wp1a = g_Wp1 + ((size_t)c * 16 + l0) * 2 * HH;
    const float* wp1b = g_Wp1 + ((size_t)c * 16 + l1) * 2 * HH;

    const int ldb = tid & 127;   // staging-load batch row
    const int seg = tid >> 7;    // staging-load k segment

    for (int t = 0; t < TT; t++) {
        const float* h0rd = g_h0 + (t & 1) * BH;
        float*       h0wr = g_h0 + ((t + 1) & 1) * BH;
        const float* h1rd = g_h1 + (t & 1) * BH;
        float*       h1wr = g_h1 + ((t + 1) & 1) * BH;

        // ================= Layer 0 =================
        unsigned long long acc[4];
        {
            size_t xa = ((size_t)t * GG + gc0) * BB + bb;
            size_t xb = ((size_t)t * GG + gc1) * BB + bb;
            acc[0] = *(const unsigned long long*)&g_xproj[xa];
            acc[1] = *(const unsigned long long*)&g_xproj[xa + 2];
            acc[2] = *(const unsigned long long*)&g_xproj[xb];
            acc[3] = *(const unsigned long long*)&g_xproj[xb + 2];
        }
        for (int kc = 0; kc < HH; kc += 64) {
            {   // stage h chunk -> s_h[k][b]
                const float* src = h0rd + (size_t)ldb * HH + kc + seg * 32;
#pragma unroll
                for (int i = 0; i < 8; i++) {
                    float4 v = __ldcg((const float4*)(src + i * 4));
                    int kl = seg * 32 + i * 4;
                    s_h[(kl + 0) * 128 + ldb] = v.x;
                    s_h[(kl + 1) * 128 + ldb] = v.y;
                    s_h[(kl + 2) * 128 + ldb] = v.z;
                    s_h[(kl + 3) * 128 + ldb] = v.w;
                }
            }
            __syncthreads();
#pragma unroll 4
            for (int k = 0; k < 64; k += 4) {
                const float4 wa = *(const float4*)(wp0a + kc + k);
                const float4 wb = *(const float4*)(wp0b + kc + k);
                float wav[4] = {wa.x, wa.y, wa.z, wa.w};
                float wbv[4] = {wb.x, wb.y, wb.z, wb.w};
#pragma unroll
                for (int kk = 0; kk < 4; kk++) {
                    const ulonglong2 h2 = *(const ulonglong2*)&s_h[(k + kk) * 128 + bb];
                    unsigned long long w2a = bcast2(wav[kk]);
                    unsigned long long w2b = bcast2(wbv[kk]);
                    acc[0] = fma2(h2.x, w2a, acc[0]);
                    acc[1] = fma2(h2.y, w2a, acc[1]);
                    acc[2] = fma2(h2.x, w2b, acc[2]);
                    acc[3] = fma2(h2.y, w2b, acc[3]);
                }
            }
            __syncthreads();
        }
        {   // gate staging + combine
            float2 v;
            v = unpk2(acc[0]); s_g[l0 * 132 + bb + 0] = v.x; s_g[l0 * 132 + bb + 1] = v.y;
            v = unpk2(acc[1]); s_g[l0 * 132 + bb + 2] = v.x; s_g[l0 * 132 + bb + 3] = v.y;
            v = unpk2(acc[2]); s_g[l1 * 132 + bb + 0] = v.x; s_g[l1 * 132 + bb + 1] = v.y;
            v = unpk2(acc[3]); s_g[l1 * 132 + bb + 2] = v.x; s_g[l1 * 132 + bb + 3] = v.y;
            __syncthreads();
#pragma unroll
            for (int rep = 0; rep < 2; rep++) {
                int idx = tid + rep * 256;
                int b = idx & 127, q = idx >> 7;
                float gi = s_g[(0 + q) * 132 + b];
                float gj = s_g[(4 + q) * 132 + b];
                float gf = s_g[(8 + q) * 132 + b];
                float go = s_g[(12 + q) * 132 + b];
                int a = b * HH + (c * 4 + q);
                float cn = g_c0[a] * sigf(gf + 1.0f) + sigf(gi) * tanhf(gj);
                g_c0[a] = cn;
                __stcg(&h0wr[a], tanhf(cn) * sigf(go));
            }
        }
        grid_barrier();

        // ================= Layer 1 =================
        acc[0] = bcast2(bias1[gc0]); acc[1] = acc[0];
        acc[2] = bcast2(bias1[gc1]); acc[3] = acc[2];
        for (int kc = 0; kc < 2 * HH; kc += 64) {
            const float* hsrc = (kc < HH) ? h0wr : h1rd;
            const int koff = (kc < HH) ? kc : (kc - HH);
            {
                const float* src = hsrc + (size_t)ldb * HH + koff + seg * 32;
#pragma unroll
                for (int i = 0; i < 8; i++) {
                    float4 v = __ldcg((const float4*)(src + i * 4));
                    int kl = seg * 32 + i * 4;
                    s_h[(kl + 0) * 128 + ldb] = v.x;
                    s_h[(kl + 1) * 128 + ldb] = v.y;
                    s_h[(kl + 2) * 128 + ldb] = v.z;
                    s_h[(kl + 3) * 128 + ldb] = v.w;
                }
            }
            __syncthreads();
#pragma unroll 4
            for (int k = 0; k < 64; k += 4) {
                const float4 wa = *(const float4*)(wp1a + kc + k);
                const float4 wb = *(const float4*)(wp1b + kc + k);
                float wav[4] = {wa.x, wa.y, wa.z, wa.w};
                float wbv[4] = {wb.x, wb.y, wb.z, wb.w};
#pragma unroll
                for (int kk = 0; kk < 4; kk++) {
                    const ulonglong2 h2 = *(const ulonglong2*)&s_h[(k + kk) * 128 + bb];
                    unsigned long long w2a = bcast2(wav[kk]);
                    unsigned long long w2b = bcast2(wbv[kk]);
                    acc[0] = fma2(h2.x, w2a, acc[0]);
                    acc[1] = fma2(h2.y, w2a, acc[1]);
                    acc[2] = fma2(h2.x, w2b, acc[2]);
                    acc[3] = fma2(h2.y, w2b, acc[3]);
                }
            }
            __syncthreads();
        }
        {
            float2 v;
            v = unpk2(acc[0]); s_g[l0 * 132 + bb + 0] = v.x; s_g[l0 * 132 + bb + 1] = v.y;
            v = unpk2(acc[1]); s_g[l0 * 132 + bb + 2] = v.x; s_g[l0 * 132 + bb + 3] = v.y;
            v = unpk2(acc[2]); s_g[l1 * 132 + bb + 0] = v.x; s_g[l1 * 132 + bb + 1] = v.y;
            v = unpk2(acc[3]); s_g[l1 * 132 + bb + 2] = v.x; s_g[l1 * 132 + bb + 3] = v.y;
            __syncthreads();
#pragma unroll
            for (int rep = 0; rep < 2; rep++) {
                int idx = tid + rep * 256;
                int b = idx & 127, q = idx >> 7;
                float gi = s_g[(0 + q) * 132 + b];
                float gj = s_g[(4 + q) * 132 + b];
                float gf = s_g[(8 + q) * 132 + b];
                float go = s_g[(12 + q) * 132 + b];
                int a = b * HH + (c * 4 + q);
                float cn = g_c1[a] * sigf(gf + 1.0f) + sigf(gi) * tanhf(gj);
                g_c1[a] = cn;
                __stcg(&h1wr[a], tanhf(cn) * sigf(go));
            }
        }
        grid_barrier();
    }

    // ---------------- final projection (T even -> h1 final lives in buffer 0) ----------------
    if (blockIdx.x == 0) {
        const int b = tid & 127, oc = tid >> 7;
        const float* hr = g_h1 + (size_t)b * HH;   // buffer 0
        float s0 = 0.f, s1 = 0.f, s2 = 0.f, s3 = 0.f;
#pragma unroll 4
        for (int k = 0; k < HH; k += 4) {
            s0 += __ldcg(hr + k + 0) * Wd[(k + 0) * 2 + oc];
            s1 += __ldcg(hr + k + 1) * Wd[(k + 1) * 2 + oc];
            s2 += __ldcg(hr + k + 2) * Wd[(k + 2) * 2 + oc];
            s3 += __ldcg(hr + k + 3) * Wd[(k + 3) * 2 + oc];
        }
        out[b * 2 + oc] = bd[oc] + ((s0 + s1) + (s2 + s3));
    }
}

// ---------------- launch ----------------
extern "C" void kernel_launch(void* const* d_in, const int* in_sizes, int n_in,
                              void* d_out, int out_size) {
    const int* xw         = (const int*)d_in[0];
    const float* emb      = (const float*)d_in[1];
    const float* W0       = (const float*)d_in[2];
    const float* b0       = (const float*)d_in[3];
    const float* W1       = (const float*)d_in[4];
    const float* b1       = (const float*)d_in[5];
    const float* Wd       = (const float*)d_in[6];
    const float* bd       = (const float*)d_in[7];
    float* out            = (float*)d_out;
    (void)n_in; (void)out_size;

    const int nx   = in_sizes[0];            // element count of x (B*T)
    const int vmax = in_sizes[1] / EE - 1;   // V - 1

    pack_kernel<<<8192, 256>>>(W0, W1);
    detect_kernel<<<(nx / 2 + 255) / 256, 256>>>(xw, nx);
    xproj_kernel<<<dim3(16, TT), 256>>>(xw, emb, W0, b0, vmax);
    lstm_kernel<<<BB, 256>>>(b1, Wd, bd, out);
}

// round 4
// speedup vs baseline: 2.2227x; 2.2227x over previous
#include <cuda_runtime.h>
#include <cstdint>
#include <math.h>

#define BB   128      // batch
#define TT   256      // timesteps
#define HH   512      // hidden
#define EE   300      // embed dim
#define GG   2048     // 4H
#define HB   (HH*BB)  // one h buffer (transposed [k][b]) = 65536 floats

// ---------------- device scratch (static, no allocation) ----------------
__device__ float g_xproj[(size_t)TT * GG * BB];   // [t][col][b]  256MB
__device__ float g_Wp0t[(size_t)GG * HH];         // [c][k4:128][cp:8][2cols x 4k]
__device__ float g_Wp1t[(size_t)GG * 2 * HH];     // [c][k4:256][cp:8][2cols x 4k]
__device__ float g_h0t[2 * HB];                   // transposed [k][b], ping-pong
__device__ float g_h1t[2 * HB];
__device__ unsigned g_bar_count;
__device__ unsigned g_bar_gen;
__device__ int g_odd_nonzero;                     // 1 -> x buffer is int32 layout

// ---------------- helpers ----------------
typedef unsigned long long ull;

__device__ __forceinline__ ull bcast2(float v) {
    ull r; asm("mov.b64 %0, {%1, %1};" : "=l"(r) : "f"(v)); return r;
}
__device__ __forceinline__ ull fma2(ull a, ull b, ull c) {
    ull d; asm("fma.rn.f32x2 %0, %1, %2, %3;" : "=l"(d) : "l"(a), "l"(b), "l"(c)); return d;
}
__device__ __forceinline__ float sigf(float x) { return 1.0f / (1.0f + expf(-x)); }

__device__ __forceinline__ void grid_barrier() {
    __syncthreads();
    if (threadIdx.x == 0) {
        __threadfence();
        unsigned gen = *((volatile unsigned*)&g_bar_gen);
        unsigned ticket = atomicAdd(&g_bar_count, 1u);
        if (ticket == gridDim.x - 1) {
            atomicExch(&g_bar_count, 0u);
            __threadfence();
            atomicAdd(&g_bar_gen, 1u);
        } else {
            while (*((volatile unsigned*)&g_bar_gen) == gen) {}
            __threadfence();
        }
    }
    __syncthreads();
}

__device__ __forceinline__ void cp16(uint32_t saddr, const float* g) {
    asm volatile("cp.async.cg.shared.global [%0], [%1], 16;" :: "r"(saddr), "l"(g));
}
__device__ __forceinline__ void cp_commit() { asm volatile("cp.async.commit_group;"); }
__device__ __forceinline__ void cp_wait1()  { asm volatile("cp.async.wait_group 1;"); }
__device__ __forceinline__ void cp_wait0()  { asm volatile("cp.async.wait_group 0;"); }

// ---------------- kernel D: detect int32 vs int64 layout of x ----------------
__global__ void detect_kernel(const int* __restrict__ xw, int nwords) {
    int i = blockIdx.x * blockDim.x + threadIdx.x;
    int odd = 2 * i + 1;
    if (odd < nwords && xw[odd] != 0) atomicOr(&g_odd_nonzero, 1);
}

// ---------------- kernel P: pack weights (warp-contiguous layout) + zero state ----------------
// Wp0t flat: ((c*128 + k4)*8 + cp)*8 + col01*4 + kk ; l = 2cp+col01 ; k = 4k4+kk
//   src = W0[(E + k)*GG + (l>>2)*512 + c*4 + (l&3)]
// Wp1t: same with k4 in [0,256), src = W1[k*GG + ...]
__global__ void pack_kernel(const float* __restrict__ W0,
                            const float* __restrict__ W1) {
    size_t i = (size_t)blockIdx.x * blockDim.x + threadIdx.x;
    const size_t N0 = (size_t)GG * HH;        // 1,048,576
    const size_t N1 = (size_t)GG * 2 * HH;    // 2,097,152
    if (i < N0) {
        int c  = (int)(i >> 13);
        int r  = (int)(i & 8191);
        int k4 = r >> 6;
        int cp = (r >> 3) & 7;
        int j  = r & 7;
        int l  = 2 * cp + (j >> 2);
        int k  = 4 * k4 + (j & 3);
        int gcol = ((l >> 2) << 9) + (c << 2) + (l & 3);
        g_Wp0t[i] = W0[(size_t)(EE + k) * GG + gcol];
    }
    if (i < N1) {
        int c  = (int)(i >> 14);
        int r  = (int)(i & 16383);
        int k4 = r >> 6;
        int cp = (r >> 3) & 7;
        int j  = r & 7;
        int l  = 2 * cp + (j >> 2);
        int k  = 4 * k4 + (j & 3);
        int gcol = ((l >> 2) << 9) + (c << 2) + (l & 3);
        g_Wp1t[i] = W1[(size_t)k * GG + gcol];
    }
    if (i < 2 * HB) { g_h0t[i] = 0.0f; g_h1t[i] = 0.0f; }
    if (i == 0) { g_bar_count = 0; g_odd_nonzero = 0; }
}

// ---------------- kernel A: xproj[t][col][b] = b0[col] + emb[x[b,t]] . W0x ----------------
__global__ void __launch_bounds__(256) xproj_kernel(const int* __restrict__ xw,
                                                    const float* __restrict__ emb,
                                                    const float* __restrict__ W0,
                                                    const float* __restrict__ bias0,
                                                    int vmax) {
    __shared__ float s_emb[88 * 128];   // [e][b], 45KB
    __shared__ int s_row[BB];
    const int t = blockIdx.y;
    const int colbase = blockIdx.x * 128;
    const int tid = threadIdx.x;

    const int stride = g_odd_nonzero ? 1 : 2;  // 1 = int32 layout, 2 = int64 layout
    if (tid < BB) {
        int idx = xw[((size_t)tid * TT + t) * stride];
        idx = idx < 0 ? 0 : (idx > vmax ? vmax : idx);
        s_row[tid] = idx;
    }

    const int cp8 = tid & 15;
    const int bg  = tid >> 4;
    const int cb  = colbase + cp8 * 8;
    const int bi  = bg * 8;

    ull acc[8][4];
#pragma unroll
    for (int c8 = 0; c8 < 8; c8++) {
        ull bv = bcast2(bias0[cb + c8]);
#pragma unroll
        for (int p = 0; p < 4; p++) acc[c8][p] = bv;
    }
    __syncthreads();

    for (int e0 = 0; e0 < EE; e0 += 88) {
        const int ec = (EE - e0 < 88) ? (EE - e0) : 88;
        const int f4cnt = ec >> 2;
        for (int fi = tid; fi < 128 * f4cnt; fi += 256) {
            int b = fi / f4cnt, j = fi % f4cnt;
            const float4 v = *(const float4*)&emb[(size_t)s_row[b] * EE + e0 + j * 4];
            s_emb[(j * 4 + 0) * 128 + b] = v.x;
            s_emb[(j * 4 + 1) * 128 + b] = v.y;
            s_emb[(j * 4 + 2) * 128 + b] = v.z;
            s_emb[(j * 4 + 3) * 128 + b] = v.w;
        }
        __syncthreads();

#pragma unroll 4
        for (int e = 0; e < ec; e++) {
            const float* wrow = W0 + (size_t)(e0 + e) * GG + cb;
            const float4 w0v = *(const float4*)wrow;
            const float4 w1v = *(const float4*)(wrow + 4);
            float wv[8] = {w0v.x, w0v.y, w0v.z, w0v.w, w1v.x, w1v.y, w1v.z, w1v.w};
            const ulonglong2 hA = *(const ulonglong2*)&s_emb[e * 128 + bi];
            const ulonglong2 hB = *(const ulonglong2*)&s_emb[e * 128 + bi + 4];
            ull hp[4] = {hA.x, hA.y, hB.x, hB.y};
#pragma unroll
            for (int c8 = 0; c8 < 8; c8++) {
                ull w2 = bcast2(wv[c8]);
#pragma unroll
                for (int p = 0; p < 4; p++) acc[c8][p] = fma2(hp[p], w2, acc[c8][p]);
            }
        }
        __syncthreads();
    }

#pragma unroll
    for (int c8 = 0; c8 < 8; c8++) {
        size_t base = ((size_t)t * GG + cb + c8) * BB + bi;
#pragma unroll
        for (int p = 0; p < 4; p++)
            *(ull*)&g_xproj[base + p * 2] = acc[c8][p];
    }
}

// ---------------- kernel B: persistent recurrent loop (v2) ----------------
// 128 CTAs x 512 threads. CTA c owns h-cols [4c,4c+4) (16 g-cols per layer).
// Software pipeline: iteration t computes L1(t) and L0(t+1) together (both
// depend only on synced state) -> ONE grid barrier per step, shared h0 chunks.
// h stored transposed [k][b] in global; staging = contiguous cp.async.cg copies.
__global__ void __launch_bounds__(512, 1) lstm_kernel(const float* __restrict__ bias1,
                                                      const float* __restrict__ Wd,
                                                      const float* __restrict__ bd,
                                                      float* __restrict__ out) {
    extern __shared__ float smem[];
    float* sbuf[2] = { smem, smem + 8192 };          // 2 x 32KB h chunks [64k][128b]
    float* s_g     = smem + 16384;                   // [16][132] gate staging

    const int c   = blockIdx.x;
    const int tid = threadIdx.x;
    const int cp  = tid & 7;          // col-pair 0..7
    const int bg  = tid >> 3;         // 0..63
    const int b0  = bg * 2;           // 2 batch rows per thread
    const int l0  = 2 * cp, l1 = 2 * cp + 1;
    const int gcl0 = ((l0 >> 2) << 9) + (c << 2) + (l0 & 3);
    const int gcl1 = ((l1 >> 2) << 9) + (c << 2) + (l1 & 3);

    // combine-thread identity: one (q, b) per thread, c-states live in registers
    const int qb_b = tid & 127;
    const int qb_q = tid >> 7;        // 0..3
    float c0reg = 0.0f, c1reg = 0.0f;
    const int hidx = (c * 4 + qb_q) * 128 + qb_b;   // transposed h offset

    const uint32_t sb_u32[2] = { (uint32_t)__cvta_generic_to_shared(sbuf[0]),
                                 (uint32_t)__cvta_generic_to_shared(sbuf[1]) };

    // ---- prologue: h0(0) = gates(xproj(0)), c_prev = 0 ----
    {
        ull a0 = *(const ull*)&g_xproj[((size_t)0 * GG + gcl0) * BB + b0];
        ull a1 = *(const ull*)&g_xproj[((size_t)0 * GG + gcl1) * BB + b0];
        *(ull*)&s_g[l0 * 132 + b0] = a0;
        *(ull*)&s_g[l1 * 132 + b0] = a1;
        __syncthreads();
        float gi = s_g[(0 * 4 + qb_q) * 132 + qb_b];
        float gj = s_g[(1 * 4 + qb_q) * 132 + qb_b];
        float go = s_g[(3 * 4 + qb_q) * 132 + qb_b];
        float cn = sigf(gi) * tanhf(gj);            // c_prev = 0
        c0reg = cn;
        __stcg(&g_h0t[0 * HB + hidx], tanhf(cn) * sigf(go));
        grid_barrier();
    }

    for (int t = 0; t < TT; t++) {
        const bool  doL0 = (t + 1 < TT);
        const int   tp1  = doL0 ? (t + 1) : t;
        const float* h0src = g_h0t + (t & 1) * HB;           // h0(t)
        const float* h1src = g_h1t + ((t + 1) & 1) * HB;     // h1(t-1)

        // acc init
        ull aL1a = bcast2(bias1[gcl0]);
        ull aL1b = bcast2(bias1[gcl1]);
        ull aL0a = __ldcg((const ull*)&g_xproj[((size_t)tp1 * GG + gcl0) * BB + b0]);
        ull aL0b = __ldcg((const ull*)&g_xproj[((size_t)tp1 * GG + gcl1) * BB + b0]);

        // prime pipeline: chunk 0
        {
            const float* g = h0src;
#pragma unroll
            for (int p = 0; p < 4; p++) cp16(sb_u32[0] + (p * 512 + tid) * 16, g + (p * 512 + tid) * 4);
            cp_commit();
        }

        for (int ch = 0; ch < 16; ch++) {
            if (ch < 15) {
                const float* g = (ch + 1 < 8) ? (h0src + (ch + 1) * 8192)
                                              : (h1src + (ch + 1 - 8) * 8192);
                uint32_t sa = sb_u32[(ch + 1) & 1];
#pragma unroll
                for (int p = 0; p < 4; p++) cp16(sa + (p * 512 + tid) * 16, g + (p * 512 + tid) * 4);
                cp_commit();
                cp_wait1();
            } else {
                cp_wait0();
            }
            __syncthreads();
            const float* sh = sbuf[ch & 1];

            if (ch < 8) {
                const int k4b = ch * 16;
                const float4* w0p = (const float4*)g_Wp0t + ((size_t)(c * 128 + k4b) * 8 + cp) * 2;
                const float4* w1p = (const float4*)g_Wp1t + ((size_t)(c * 256 + k4b) * 8 + cp) * 2;
#pragma unroll 4
                for (int j = 0; j < 16; j++) {
                    const float4 wA = w0p[j * 16 + 0];
                    const float4 wB = w0p[j * 16 + 1];
                    const float4 wC = w1p[j * 16 + 0];
                    const float4 wD = w1p[j * 16 + 1];
                    const float wAv[4] = {wA.x, wA.y, wA.z, wA.w};
                    const float wBv[4] = {wB.x, wB.y, wB.z, wB.w};
                    const float wCv[4] = {wC.x, wC.y, wC.z, wC.w};
                    const float wDv[4] = {wD.x, wD.y, wD.z, wD.w};
#pragma unroll
                    for (int kk = 0; kk < 4; kk++) {
                        ull h2 = *(const ull*)&sh[(j * 4 + kk) * 128 + b0];
                        aL0a = fma2(h2, bcast2(wAv[kk]), aL0a);
                        aL0b = fma2(h2, bcast2(wBv[kk]), aL0b);
                        aL1a = fma2(h2, bcast2(wCv[kk]), aL1a);
                        aL1b = fma2(h2, bcast2(wDv[kk]), aL1b);
                    }
                }
            } else {
                const int k4b = 128 + (ch - 8) * 16;
                const float4* w1p = (const float4*)g_Wp1t + ((size_t)(c * 256 + k4b) * 8 + cp) * 2;
#pragma unroll 4
                for (int j = 0; j < 16; j++) {
                    const float4 wC = w1p[j * 16 + 0];
                    const float4 wD = w1p[j * 16 + 1];
                    const float wCv[4] = {wC.x, wC.y, wC.z, wC.w};
                    const float wDv[4] = {wD.x, wD.y, wD.z, wD.w};
#pragma unroll
                    for (int kk = 0; kk < 4; kk++) {
                        ull h2 = *(const ull*)&sh[(j * 4 + kk) * 128 + b0];
                        aL1a = fma2(h2, bcast2(wCv[kk]), aL1a);
                        aL1b = fma2(h2, bcast2(wDv[kk]), aL1b);
                    }
                }
            }
            __syncthreads();
        }

        // ---- L1(t) gates -> h1(t) into buf[t&1] ----
        *(ull*)&s_g[l0 * 132 + b0] = aL1a;
        *(ull*)&s_g[l1 * 132 + b0] = aL1b;
        __syncthreads();
        {
            float gi = s_g[(0 * 4 + qb_q) * 132 + qb_b];
            float gj = s_g[(1 * 4 + qb_q) * 132 + qb_b];
            float gf = s_g[(2 * 4 + qb_q) * 132 + qb_b];
            float go = s_g[(3 * 4 + qb_q) * 132 + qb_b];
            float cn = c1reg * sigf(gf + 1.0f) + sigf(gi) * tanhf(gj);
            c1reg = cn;
            __stcg(&g_h1t[(t & 1) * HB + hidx], tanhf(cn) * sigf(go));
        }
        __syncthreads();

        // ---- L0(t+1) gates -> h0(t+1) into buf[(t+1)&1] ----
        if (doL0) {
            *(ull*)&s_g[l0 * 132 + b0] = aL0a;
            *(ull*)&s_g[l1 * 132 + b0] = aL0b;
            __syncthreads();
            float gi = s_g[(0 * 4 + qb_q) * 132 + qb_b];
            float gj = s_g[(1 * 4 + qb_q) * 132 + qb_b];
            float gf = s_g[(2 * 4 + qb_q) * 132 + qb_b];
            float go = s_g[(3 * 4 + qb_q) * 132 + qb_b];
            float cn = c0reg * sigf(gf + 1.0f) + sigf(gi) * tanhf(gj);
            c0reg = cn;
            __stcg(&g_h0t[((t + 1) & 1) * HB + hidx], tanhf(cn) * sigf(go));
        }
        grid_barrier();
    }

    // ---- final projection: logits = h1(T-1) . Wd + bd ; h1(T-1) in buf[(TT-1)&1] ----
    if (blockIdx.x == 0 && tid < 256) {
        const int b = tid & 127, oc = tid >> 7;
        const float* hf = g_h1t + ((TT - 1) & 1) * HB;
        float s = 0.0f;
#pragma unroll 8
        for (int k = 0; k < HH; k++)
            s += __ldcg(&hf[k * 128 + b]) * Wd[k * 2 + oc];
        out[b * 2 + oc] = s + bd[oc];
    }
}

// ---------------- launch ----------------
extern "C" void kernel_launch(void* const* d_in, const int* in_sizes, int n_in,
                              void* d_out, int out_size) {
    const int* xw    = (const int*)d_in[0];
    const float* emb = (const float*)d_in[1];
    const float* W0  = (const float*)d_in[2];
    const float* b0  = (const float*)d_in[3];
    const float* W1  = (const float*)d_in[4];
    const float* b1  = (const float*)d_in[5];
    const float* Wd  = (const float*)d_in[6];
    const float* bd  = (const float*)d_in[7];
    float* out       = (float*)d_out;
    (void)n_in; (void)out_size;

    const int nx   = in_sizes[0];
    const int vmax = in_sizes[1] / EE - 1;

    const int smemBytes = (2 * 8192 + 16 * 132) * sizeof(float);   // 73984
    cudaFuncSetAttribute(lstm_kernel, cudaFuncAttributeMaxDynamicSharedMemorySize, smemBytes);

    pack_kernel<<<8192, 256>>>(W0, W1);
    detect_kernel<<<(nx / 2 + 255) / 256, 256>>>(xw, nx);
    xproj_kernel<<<dim3(16, TT), 256>>>(xw, emb, W0, b0, vmax);
    lstm_kernel<<<BB, 512, smemBytes>>>(b1, Wd, bd, out);
}

// round 5
// speedup vs baseline: 2.8123x; 1.2652x over previous
#include <cuda_runtime.h>
#include <cstdint>
#include <math.h>

#define BB   128      // batch
#define TT   256      // timesteps
#define HH   512      // hidden
#define EE   300      // embed dim
#define GG   2048     // 4H
#define HB   (HH*BB)  // one h buffer (transposed [k][b]) = 65536 floats

// ---------------- device scratch (static, no allocation) ----------------
__device__ float g_xproj[(size_t)TT * GG * BB];   // [t][col][b]  256MB
__device__ float g_Wp0t[(size_t)GG * HH];         // [c][k4:128][cp:8][2cols x 4k]
__device__ float g_Wp1t[(size_t)GG * 2 * HH];     // [c][k4:256][cp:8][2cols x 4k]
__device__ float g_h0t[2 * HB];                   // transposed [k][b], ping-pong
__device__ float g_h1t[2 * HB];
__device__ unsigned g_bar_count;
__device__ unsigned g_bar_gen;
__device__ int g_odd_nonzero;                     // 1 -> x buffer is int32 layout

// ---------------- helpers ----------------
typedef unsigned long long ull;

__device__ __forceinline__ ull bcast2(float v) {
    ull r; asm("mov.b64 %0, {%1, %1};" : "=l"(r) : "f"(v)); return r;
}
__device__ __forceinline__ ull fma2(ull a, ull b, ull c) {
    ull d; asm("fma.rn.f32x2 %0, %1, %2, %3;" : "=l"(d) : "l"(a), "l"(b), "l"(c)); return d;
}
__device__ __forceinline__ float sigf(float x) { return 1.0f / (1.0f + expf(-x)); }

__device__ __forceinline__ void grid_barrier() {
    __syncthreads();
    if (threadIdx.x == 0) {
        __threadfence();
        unsigned gen = *((volatile unsigned*)&g_bar_gen);
        unsigned ticket = atomicAdd(&g_bar_count, 1u);
        if (ticket == gridDim.x - 1) {
            atomicExch(&g_bar_count, 0u);
            __threadfence();
            atomicAdd(&g_bar_gen, 1u);
        } else {
            while (*((volatile unsigned*)&g_bar_gen) == gen) {}
            __threadfence();
        }
    }
    __syncthreads();
}

__device__ __forceinline__ void cp16(uint32_t saddr, const float* g) {
    asm volatile("cp.async.cg.shared.global [%0], [%1], 16;" :: "r"(saddr), "l"(g));
}
__device__ __forceinline__ void cp_commit() { asm volatile("cp.async.commit_group;"); }
__device__ __forceinline__ void cp_wait1()  { asm volatile("cp.async.wait_group 1;"); }
__device__ __forceinline__ void cp_wait0()  { asm volatile("cp.async.wait_group 0;"); }

// ---------------- kernel D: detect int32 vs int64 layout of x ----------------
__global__ void detect_kernel(const int* __restrict__ xw, int nwords) {
    int i = blockIdx.x * blockDim.x + threadIdx.x;
    int odd = 2 * i + 1;
    if (odd < nwords && xw[odd] != 0) atomicOr(&g_odd_nonzero, 1);
}

// ---------------- kernel P: pack weights + zero state ----------------
__global__ void pack_kernel(const float* __restrict__ W0,
                            const float* __restrict__ W1) {
    size_t i = (size_t)blockIdx.x * blockDim.x + threadIdx.x;
    const size_t N0 = (size_t)GG * HH;        // 1,048,576
    const size_t N1 = (size_t)GG * 2 * HH;    // 2,097,152
    if (i < N0) {
        int c  = (int)(i >> 13);
        int r  = (int)(i & 8191);
        int k4 = r >> 6;
        int cp = (r >> 3) & 7;
        int j  = r & 7;
        int l  = 2 * cp + (j >> 2);
        int k  = 4 * k4 + (j & 3);
        int gcol = ((l >> 2) << 9) + (c << 2) + (l & 3);
        g_Wp0t[i] = W0[(size_t)(EE + k) * GG + gcol];
    }
    if (i < N1) {
        int c  = (int)(i >> 14);
        int r  = (int)(i & 16383);
        int k4 = r >> 6;
        int cp = (r >> 3) & 7;
        int j  = r & 7;
        int l  = 2 * cp + (j >> 2);
        int k  = 4 * k4 + (j & 3);
        int gcol = ((l >> 2) << 9) + (c << 2) + (l & 3);
        g_Wp1t[i] = W1[(size_t)k * GG + gcol];
    }
    if (i < 2 * HB) { g_h0t[i] = 0.0f; g_h1t[i] = 0.0f; }
    if (i == 0) { g_bar_count = 0; g_odd_nonzero = 0; }
}

// ---------------- kernel A: xproj[t][col][b] ----------------
__global__ void __launch_bounds__(256) xproj_kernel(const int* __restrict__ xw,
                                                    const float* __restrict__ emb,
                                                    const float* __restrict__ W0,
                                                    const float* __restrict__ bias0,
                                                    int vmax) {
    __shared__ float s_emb[88 * 128];
    __shared__ int s_row[BB];
    const int t = blockIdx.y;
    const int colbase = blockIdx.x * 128;
    const int tid = threadIdx.x;

    const int stride = g_odd_nonzero ? 1 : 2;
    if (tid < BB) {
        int idx = xw[((size_t)tid * TT + t) * stride];
        idx = idx < 0 ? 0 : (idx > vmax ? vmax : idx);
        s_row[tid] = idx;
    }

    const int cp8 = tid & 15;
    const int bg  = tid >> 4;
    const int cb  = colbase + cp8 * 8;
    const int bi  = bg * 8;

    ull acc[8][4];
#pragma unroll
    for (int c8 = 0; c8 < 8; c8++) {
        ull bv = bcast2(bias0[cb + c8]);
#pragma unroll
        for (int p = 0; p < 4; p++) acc[c8][p] = bv;
    }
    __syncthreads();

    for (int e0 = 0; e0 < EE; e0 += 88) {
        const int ec = (EE - e0 < 88) ? (EE - e0) : 88;
        const int f4cnt = ec >> 2;
        for (int fi = tid; fi < 128 * f4cnt; fi += 256) {
            int b = fi / f4cnt, j = fi % f4cnt;
            const float4 v = *(const float4*)&emb[(size_t)s_row[b] * EE + e0 + j * 4];
            s_emb[(j * 4 + 0) * 128 + b] = v.x;
            s_emb[(j * 4 + 1) * 128 + b] = v.y;
            s_emb[(j * 4 + 2) * 128 + b] = v.z;
            s_emb[(j * 4 + 3) * 128 + b] = v.w;
        }
        __syncthreads();

#pragma unroll 4
        for (int e = 0; e < ec; e++) {
            const float* wrow = W0 + (size_t)(e0 + e) * GG + cb;
            const float4 w0v = *(const float4*)wrow;
            const float4 w1v = *(const float4*)(wrow + 4);
            float wv[8] = {w0v.x, w0v.y, w0v.z, w0v.w, w1v.x, w1v.y, w1v.z, w1v.w};
            const ulonglong2 hA = *(const ulonglong2*)&s_emb[e * 128 + bi];
            const ulonglong2 hB = *(const ulonglong2*)&s_emb[e * 128 + bi + 4];
            ull hp[4] = {hA.x, hA.y, hB.x, hB.y};
#pragma unroll
            for (int c8 = 0; c8 < 8; c8++) {
                ull w2 = bcast2(wv[c8]);
#pragma unroll
                for (int p = 0; p < 4; p++) acc[c8][p] = fma2(hp[p], w2, acc[c8][p]);
            }
        }
        __syncthreads();
    }

#pragma unroll
    for (int c8 = 0; c8 < 8; c8++) {
        size_t base = ((size_t)t * GG + cb + c8) * BB + bi;
#pragma unroll
        for (int p = 0; p < 4; p++)
            *(ull*)&g_xproj[base + p * 2] = acc[c8][p];
    }
}

// ---------------- kernel B: persistent recurrent loop (v3) ----------------
// 128 CTAs x 256 threads. CTA c owns h-cols [4c,4c+4) (16 g-cols per layer).
// Register tile per thread: 2 g-cols x 4 batches per layer -> weight LDG and
// h LDS traffic both halved vs v2 at the same fma2 issue floor.
// Pipelined: iteration t computes L1(t) and L0(t+1) -> one grid barrier/step.
__global__ void __launch_bounds__(256, 1) lstm_kernel(const float* __restrict__ bias1,
                                                      const float* __restrict__ Wd,
                                                      const float* __restrict__ bd,
                                                      float* __restrict__ out) {
    extern __shared__ float smem[];
    float* sbuf[2] = { smem, smem + 8192 };          // 2 x 32KB h chunks [64k][128b]
    float* s_g     = smem + 16384;                   // [16][132] gate staging

    const int c   = blockIdx.x;
    const int tid = threadIdx.x;
    const int cp  = tid & 7;          // col-pair 0..7
    const int bg  = tid >> 3;         // 0..31
    const int b0  = bg * 4;           // 4 batch rows per thread
    const int l0  = 2 * cp, l1 = 2 * cp + 1;
    const int gcl0 = ((l0 >> 2) << 9) + (c << 2) + (l0 & 3);
    const int gcl1 = ((l1 >> 2) << 9) + (c << 2) + (l1 & 3);

    const ull biasA = bcast2(bias1[gcl0]);
    const ull biasB = bcast2(bias1[gcl1]);

    // combine-thread identity: two (q, b) pairs per thread, c-states in regs
    float c0reg[2] = {0.0f, 0.0f}, c1reg[2] = {0.0f, 0.0f};
    int hidx[2], qv[2], bv[2];
#pragma unroll
    for (int rep = 0; rep < 2; rep++) {
        int idx = tid + rep * 256;
        bv[rep] = idx & 127;
        qv[rep] = idx >> 7;          // 0..3
        hidx[rep] = (c * 4 + qv[rep]) * 128 + bv[rep];
    }

    const float4* w0base = (const float4*)g_Wp0t + (size_t)c * 128 * 16;
    const float4* w1base = (const float4*)g_Wp1t + (size_t)c * 256 * 16;

    const uint32_t sb_u32[2] = { (uint32_t)__cvta_generic_to_shared(sbuf[0]),
                                 (uint32_t)__cvta_generic_to_shared(sbuf[1]) };

    // ---- prologue: h0(0) = gates(xproj(0)), c_prev = 0 ----
    {
        size_t xa = ((size_t)0 * GG + gcl0) * BB + b0;
        size_t xb = ((size_t)0 * GG + gcl1) * BB + b0;
        *(ull*)&s_g[l0 * 132 + b0]     = *(const ull*)&g_xproj[xa];
        *(ull*)&s_g[l0 * 132 + b0 + 2] = *(const ull*)&g_xproj[xa + 2];
        *(ull*)&s_g[l1 * 132 + b0]     = *(const ull*)&g_xproj[xb];
        *(ull*)&s_g[l1 * 132 + b0 + 2] = *(const ull*)&g_xproj[xb + 2];
        __syncthreads();
#pragma unroll
        for (int rep = 0; rep < 2; rep++) {
            float gi = s_g[(0 * 4 + qv[rep]) * 132 + bv[rep]];
            float gj = s_g[(1 * 4 + qv[rep]) * 132 + bv[rep]];
            float go = s_g[(3 * 4 + qv[rep]) * 132 + bv[rep]];
            float cn = sigf(gi) * tanhf(gj);       // c_prev = 0
            c0reg[rep] = cn;
            __stcg(&g_h0t[0 * HB + hidx[rep]], tanhf(cn) * sigf(go));
        }
        grid_barrier();
    }

    for (int t = 0; t < TT; t++) {
        const bool  doL0 = (t + 1 < TT);
        const int   tp1  = doL0 ? (t + 1) : t;
        const float* h0src = g_h0t + (t & 1) * HB;           // h0(t)
        const float* h1src = g_h1t + ((t + 1) & 1) * HB;     // h1(t-1)

        // accumulators: [col][pair-of-2-batches]
        ull aL1[2][2] = {{biasA, biasA}, {biasB, biasB}};
        ull aL0[2][2];
        {
            size_t xa = ((size_t)tp1 * GG + gcl0) * BB + b0;
            size_t xb = ((size_t)tp1 * GG + gcl1) * BB + b0;
            aL0[0][0] = __ldcg((const ull*)&g_xproj[xa]);
            aL0[0][1] = __ldcg((const ull*)&g_xproj[xa + 2]);
            aL0[1][0] = __ldcg((const ull*)&g_xproj[xb]);
            aL0[1][1] = __ldcg((const ull*)&g_xproj[xb + 2]);
        }

        // prime pipeline: chunk 0
        {
            const float* g = h0src;
#pragma unroll
            for (int p = 0; p < 8; p++) cp16(sb_u32[0] + (p * 256 + tid) * 16, g + (p * 256 + tid) * 4);
            cp_commit();
        }

        for (int ch = 0; ch < 16; ch++) {
            if (ch < 15) {
                const float* g = (ch + 1 < 8) ? (h0src + (ch + 1) * 8192)
                                              : (h1src + (ch + 1 - 8) * 8192);
                uint32_t sa = sb_u32[(ch + 1) & 1];
#pragma unroll
                for (int p = 0; p < 8; p++) cp16(sa + (p * 256 + tid) * 16, g + (p * 256 + tid) * 4);
                cp_commit();
                cp_wait1();
            } else {
                cp_wait0();
            }
            __syncthreads();
            const float* sh = sbuf[ch & 1];

            if (ch < 8) {
                const float4* w0p = w0base + ((size_t)(ch * 16) * 8 + cp) * 2;
                const float4* w1p = w1base + ((size_t)(ch * 16) * 8 + cp) * 2;
#pragma unroll 4
                for (int j = 0; j < 16; j++) {
                    const float4 wA = w0p[j * 16 + 0];
                    const float4 wB = w0p[j * 16 + 1];
                    const float4 wC = w1p[j * 16 + 0];
                    const float4 wD = w1p[j * 16 + 1];
                    const float wAv[4] = {wA.x, wA.y, wA.z, wA.w};
                    const float wBv[4] = {wB.x, wB.y, wB.z, wB.w};
                    const float wCv[4] = {wC.x, wC.y, wC.z, wC.w};
                    const float wDv[4] = {wD.x, wD.y, wD.z, wD.w};
#pragma unroll
                    for (int kk = 0; kk < 4; kk++) {
                        const ulonglong2 h2 = *(const ulonglong2*)&sh[(j * 4 + kk) * 128 + b0];
                        ull wa = bcast2(wAv[kk]), wb = bcast2(wBv[kk]);
                        ull wc = bcast2(wCv[kk]), wd = bcast2(wDv[kk]);
                        aL0[0][0] = fma2(h2.x, wa, aL0[0][0]);
                        aL0[0][1] = fma2(h2.y, wa, aL0[0][1]);
                        aL0[1][0] = fma2(h2.x, wb, aL0[1][0]);
                        aL0[1][1] = fma2(h2.y, wb, aL0[1][1]);
                        aL1[0][0] = fma2(h2.x, wc, aL1[0][0]);
                        aL1[0][1] = fma2(h2.y, wc, aL1[0][1]);
                        aL1[1][0] = fma2(h2.x, wd, aL1[1][0]);
                        aL1[1][1] = fma2(h2.y, wd, aL1[1][1]);
                    }
                }
            } else {
                const float4* w1p = w1base + ((size_t)(128 + (ch - 8) * 16) * 8 + cp) * 2;
#pragma unroll 4
                for (int j = 0; j < 16; j++) {
                    const float4 wC = w1p[j * 16 + 0];
                    const float4 wD = w1p[j * 16 + 1];
                    const float wCv[4] = {wC.x, wC.y, wC.z, wC.w};
                    const float wDv[4] = {wD.x, wD.y, wD.z, wD.w};
#pragma unroll
                    for (int kk = 0; kk < 4; kk++) {
                        const ulonglong2 h2 = *(const ulonglong2*)&sh[(j * 4 + kk) * 128 + b0];
                        ull wc = bcast2(wCv[kk]), wd = bcast2(wDv[kk]);
                        aL1[0][0] = fma2(h2.x, wc, aL1[0][0]);
                        aL1[0][1] = fma2(h2.y, wc, aL1[0][1]);
                        aL1[1][0] = fma2(h2.x, wd, aL1[1][0]);
                        aL1[1][1] = fma2(h2.y, wd, aL1[1][1]);
                    }
                }
            }
            __syncthreads();
        }

        // ---- L1(t) gates -> h1(t) ----
        *(ull*)&s_g[l0 * 132 + b0]     = aL1[0][0];
        *(ull*)&s_g[l0 * 132 + b0 + 2] = aL1[0][1];
        *(ull*)&s_g[l1 * 132 + b0]     = aL1[1][0];
        *(ull*)&s_g[l1 * 132 + b0 + 2] = aL1[1][1];
        __syncthreads();
#pragma unroll
        for (int rep = 0; rep < 2; rep++) {
            float gi = s_g[(0 * 4 + qv[rep]) * 132 + bv[rep]];
            float gj = s_g[(1 * 4 + qv[rep]) * 132 + bv[rep]];
            float gf = s_g[(2 * 4 + qv[rep]) * 132 + bv[rep]];
            float go = s_g[(3 * 4 + qv[rep]) * 132 + bv[rep]];
            float cn = c1reg[rep] * sigf(gf + 1.0f) + sigf(gi) * tanhf(gj);
            c1reg[rep] = cn;
            __stcg(&g_h1t[(t & 1) * HB + hidx[rep]], tanhf(cn) * sigf(go));
        }
        __syncthreads();

        // ---- L0(t+1) gates -> h0(t+1) ----
        if (doL0) {
            *(ull*)&s_g[l0 * 132 + b0]     = aL0[0][0];
            *(ull*)&s_g[l0 * 132 + b0 + 2] = aL0[0][1];
            *(ull*)&s_g[l1 * 132 + b0]     = aL0[1][0];
            *(ull*)&s_g[l1 * 132 + b0 + 2] = aL0[1][1];
            __syncthreads();
#pragma unroll
            for (int rep = 0; rep < 2; rep++) {
                float gi = s_g[(0 * 4 + qv[rep]) * 132 + bv[rep]];
                float gj = s_g[(1 * 4 + qv[rep]) * 132 + bv[rep]];
                float gf = s_g[(2 * 4 + qv[rep]) * 132 + bv[rep]];
                float go = s_g[(3 * 4 + qv[rep]) * 132 + bv[rep]];
                float cn = c0reg[rep] * sigf(gf + 1.0f) + sigf(gi) * tanhf(gj);
                c0reg[rep] = cn;
                __stcg(&g_h0t[((t + 1) & 1) * HB + hidx[rep]], tanhf(cn) * sigf(go));
            }
        }
        grid_barrier();
    }

    // ---- final projection: logits = h1(T-1) . Wd + bd ----
    if (blockIdx.x == 0) {
        const int b = tid & 127, oc = tid >> 7;
        const float* hf = g_h1t + ((TT - 1) & 1) * HB;
        float s = 0.0f;
#pragma unroll 8
        for (int k = 0; k < HH; k++)
            s += __ldcg(&hf[k * 128 + b]) * Wd[k * 2 + oc];
        out[b * 2 + oc] = s + bd[oc];
    }
}

// ---------------- launch ----------------
extern "C" void kernel_launch(void* const* d_in, const int* in_sizes, int n_in,
                              void* d_out, int out_size) {
    const int* xw    = (const int*)d_in[0];
    const float* emb = (const float*)d_in[1];
    const float* W0  = (const float*)d_in[2];
    const float* b0  = (const float*)d_in[3];
    const float* W1  = (const float*)d_in[4];
    const float* b1  = (const float*)d_in[5];
    const float* Wd  = (const float*)d_in[6];
    const float* bd  = (const float*)d_in[7];
    float* out       = (float*)d_out;
    (void)n_in; (void)out_size;

    const int nx   = in_sizes[0];
    const int vmax = in_sizes[1] / EE - 1;

    const int smemBytes = (2 * 8192 + 16 * 132) * sizeof(float);   // 73984
    cudaFuncSetAttribute(lstm_kernel, cudaFuncAttributeMaxDynamicSharedMemorySize, smemBytes);

    pack_kernel<<<8192, 256>>>(W0, W1);
    detect_kernel<<<(nx / 2 + 255) / 256, 256>>>(xw, nx);
    xproj_kernel<<<dim3(16, TT), 256>>>(xw, emb, W0, b0, vmax);
    lstm_kernel<<<BB, 256, smemBytes>>>(b1, Wd, bd, out);
}